// round 16
// baseline (speedup 1.0000x reference)
#include <cuda_runtime.h>
#include <cuda_bf16.h>
#include <cstdint>

#define N_TOK 10368
#define CDIM  256
#define HDIM  128
#define NZ    54          // token chunks of 192 for Gpart

// ---------------- scratch ----------------
__device__ __align__(16) __nv_bfloat16 g_feat_h[(size_t)CDIM * N_TOK];
__device__ __align__(16) __nv_bfloat16 g_feat_l[(size_t)CDIM * N_TOK];
__device__ __align__(16) __nv_bfloat16 g_Wh[(size_t)CDIM * CDIM];   // rows 0-127 Wi, 128-255 Wj
__device__ __align__(16) __nv_bfloat16 g_Wl[(size_t)CDIM * CDIM];
__device__ __align__(16) __nv_bfloat16 g_Fh[(size_t)CDIM * N_TOK];  // rows 0-127 Fi, 128-255 Fj
__device__ __align__(16) __nv_bfloat16 g_Fl[(size_t)HDIM * N_TOK];  // Fi lo only
__device__ float g_Gpart [(size_t)NZ * HDIM * CDIM];                // [z][p][q] fp32
__device__ float g_Gpart2[(size_t)18 * HDIM * CDIM];                // stage-2 partials
__device__ __align__(16) __nv_bfloat16 g_Gh[(size_t)HDIM * CDIM];   // G/N bf16 hi only

// ---------------- helpers ----------------
__device__ __forceinline__ uint32_t smem_u32(const void* p) {
    uint32_t a;
    asm("{ .reg .u64 t; cvta.to.shared.u64 t, %1; cvt.u32.u64 %0, t; }" : "=r"(a) : "l"(p));
    return a;
}
__device__ __forceinline__ void ldsm4(uint32_t* r, uint32_t a) {
    asm volatile("ldmatrix.sync.aligned.m8n8.x4.shared.b16 {%0,%1,%2,%3}, [%4];"
                 : "=r"(r[0]), "=r"(r[1]), "=r"(r[2]), "=r"(r[3]) : "r"(a));
}
__device__ __forceinline__ void ldsm4t(uint32_t* r, uint32_t a) {
    asm volatile("ldmatrix.sync.aligned.m8n8.x4.trans.shared.b16 {%0,%1,%2,%3}, [%4];"
                 : "=r"(r[0]), "=r"(r[1]), "=r"(r[2]), "=r"(r[3]) : "r"(a));
}
__device__ __forceinline__ void mma_bf16(float* d, const uint32_t* a, const uint32_t* b) {
    asm volatile("mma.sync.aligned.m16n8k16.row.col.f32.bf16.bf16.f32 "
                 "{%0,%1,%2,%3}, {%4,%5,%6,%7}, {%8,%9}, {%0,%1,%2,%3};"
                 : "+f"(d[0]), "+f"(d[1]), "+f"(d[2]), "+f"(d[3])
                 : "r"(a[0]), "r"(a[1]), "r"(a[2]), "r"(a[3]), "r"(b[0]), "r"(b[1]));
}
__device__ __forceinline__ void cpa16(uint32_t dst, const void* src) {
    asm volatile("cp.async.cg.shared.global [%0], [%1], 16;" :: "r"(dst), "l"(src));
}
#define CP_COMMIT() asm volatile("cp.async.commit_group;" ::: "memory")
#define CP_WAIT0()  asm volatile("cp.async.wait_group 0;" ::: "memory")
#define CP_WAIT1()  asm volatile("cp.async.wait_group 1;" ::: "memory")

__device__ __forceinline__ void split4(float4 v, uint2& h, uint2& l) {
    __nv_bfloat16 h0 = __float2bfloat16_rn(v.x), h1 = __float2bfloat16_rn(v.y),
                  h2 = __float2bfloat16_rn(v.z), h3 = __float2bfloat16_rn(v.w);
    float l0 = v.x - __bfloat162float(h0), l1 = v.y - __bfloat162float(h1),
          l2 = v.z - __bfloat162float(h2), l3 = v.w - __bfloat162float(h3);
    h.x = (uint32_t)__bfloat16_as_ushort(h0) | ((uint32_t)__bfloat16_as_ushort(h1) << 16);
    h.y = (uint32_t)__bfloat16_as_ushort(h2) | ((uint32_t)__bfloat16_as_ushort(h3) << 16);
    l.x = (uint32_t)__bfloat16_as_ushort(__float2bfloat16_rn(l0)) |
          ((uint32_t)__bfloat16_as_ushort(__float2bfloat16_rn(l1)) << 16);
    l.y = (uint32_t)__bfloat16_as_ushort(__float2bfloat16_rn(l2)) |
          ((uint32_t)__bfloat16_as_ushort(__float2bfloat16_rn(l3)) << 16);
}
__device__ __forceinline__ uint2 hi4(float4 v) {
    __nv_bfloat16 h0 = __float2bfloat16_rn(v.x), h1 = __float2bfloat16_rn(v.y),
                  h2 = __float2bfloat16_rn(v.z), h3 = __float2bfloat16_rn(v.w);
    uint2 h;
    h.x = (uint32_t)__bfloat16_as_ushort(h0) | ((uint32_t)__bfloat16_as_ushort(h1) << 16);
    h.y = (uint32_t)__bfloat16_as_ushort(h2) | ((uint32_t)__bfloat16_as_ushort(h3) << 16);
    return h;
}

template<int ROWS, int KW>
__device__ __forceinline__ void stage_cp(uint32_t dst, const __nv_bfloat16* __restrict__ src,
                                         int ld, int tid)
{
    constexpr int RV = KW / 8;
    #pragma unroll
    for (int i = tid; i < ROWS * RV; i += 256) {
        int r = i / RV, c = (i % RV) * 8;
        cpa16(dst + (uint32_t)(r * (KW + 8) + c) * 2, src + (size_t)r * ld + c);
    }
}

// address setup shared by both MMA variants
template<bool AT, bool BT, int ASTR, int BSTR>
__device__ __forceinline__ void mma_addr(int warp_m, int warp_n, int lane,
                                         uint32_t& aBase, uint32_t& aStep, uint32_t& aM16,
                                         uint32_t& bBase, uint32_t& bStep, uint32_t& bN16)
{
    const int q = lane >> 3, rr = lane & 7;
    if (!AT) { aBase = (uint32_t)((warp_m + (q & 1) * 8 + rr) * ASTR + (q >> 1) * 8) * 2;
               aStep = 32; aM16 = 16 * ASTR * 2; }
    else     { aBase = (uint32_t)(((q >> 1) * 8 + rr) * ASTR + warp_m + (q & 1) * 8) * 2;
               aStep = 16 * ASTR * 2; aM16 = 32; }
    if (!BT) { bBase = (uint32_t)((warp_n + (q >> 1) * 8 + rr) * BSTR + (q & 1) * 8) * 2;
               bStep = 32; bN16 = 16 * BSTR * 2; }
    else     { bBase = (uint32_t)(((q & 1) * 8 + rr) * BSTR + warp_n + (q >> 1) * 8) * 2;
               bStep = 16 * BSTR * 2; bN16 = 32; }
}

// 3-term: acc += Ah*Bh + Ah*Bl + Al*Bh
template<int MF, int NF2, bool AT, bool BT, int ASTR, int BSTR>
__device__ __forceinline__ void mma_chunk3(float acc[MF][NF2 * 2][4],
                                           uint32_t aHi, uint32_t aLo,
                                           uint32_t bHi, uint32_t bLo,
                                           int warp_m, int warp_n, int lane)
{
    uint32_t aBase, aStep, aM16, bBase, bStep, bN16;
    mma_addr<AT, BT, ASTR, BSTR>(warp_m, warp_n, lane, aBase, aStep, aM16, bBase, bStep, bN16);

    #pragma unroll
    for (int ks = 0; ks < 2; ++ks) {
        uint32_t ah[MF][4], al[MF][4], bh[NF2][4], bl[NF2][4];
        uint32_t aA = aBase + ks * aStep, bA = bBase + ks * bStep;
        #pragma unroll
        for (int i = 0; i < MF; ++i) {
            if (AT) { ldsm4t(ah[i], aHi + aA + i * aM16); ldsm4t(al[i], aLo + aA + i * aM16); }
            else    { ldsm4 (ah[i], aHi + aA + i * aM16); ldsm4 (al[i], aLo + aA + i * aM16); }
        }
        #pragma unroll
        for (int g = 0; g < NF2; ++g) {
            if (BT) { ldsm4t(bh[g], bHi + bA + g * bN16); ldsm4t(bl[g], bLo + bA + g * bN16); }
            else    { ldsm4 (bh[g], bHi + bA + g * bN16); ldsm4 (bl[g], bLo + bA + g * bN16); }
        }
        #pragma unroll
        for (int i = 0; i < MF; ++i)
            #pragma unroll
            for (int j = 0; j < NF2 * 2; ++j) {
                mma_bf16(acc[i][j], ah[i], &bh[j >> 1][(j & 1) * 2]);
                mma_bf16(acc[i][j], ah[i], &bl[j >> 1][(j & 1) * 2]);
                mma_bf16(acc[i][j], al[i], &bh[j >> 1][(j & 1) * 2]);
            }
    }
}

// 2-term (A hi only): acc += Ah*Bh + Ah*Bl
template<int MF, int NF2, bool AT, bool BT, int ASTR, int BSTR>
__device__ __forceinline__ void mma_chunk2(float acc[MF][NF2 * 2][4],
                                           uint32_t aHi,
                                           uint32_t bHi, uint32_t bLo,
                                           int warp_m, int warp_n, int lane)
{
    uint32_t aBase, aStep, aM16, bBase, bStep, bN16;
    mma_addr<AT, BT, ASTR, BSTR>(warp_m, warp_n, lane, aBase, aStep, aM16, bBase, bStep, bN16);

    #pragma unroll
    for (int ks = 0; ks < 2; ++ks) {
        uint32_t ah[MF][4], bh[NF2][4], bl[NF2][4];
        uint32_t aA = aBase + ks * aStep, bA = bBase + ks * bStep;
        #pragma unroll
        for (int i = 0; i < MF; ++i) {
            if (AT) ldsm4t(ah[i], aHi + aA + i * aM16);
            else    ldsm4 (ah[i], aHi + aA + i * aM16);
        }
        #pragma unroll
        for (int g = 0; g < NF2; ++g) {
            if (BT) { ldsm4t(bh[g], bHi + bA + g * bN16); ldsm4t(bl[g], bLo + bA + g * bN16); }
            else    { ldsm4 (bh[g], bHi + bA + g * bN16); ldsm4 (bl[g], bLo + bA + g * bN16); }
        }
        #pragma unroll
        for (int i = 0; i < MF; ++i)
            #pragma unroll
            for (int j = 0; j < NF2 * 2; ++j) {
                mma_bf16(acc[i][j], ah[i], &bh[j >> 1][(j & 1) * 2]);
                mma_bf16(acc[i][j], ah[i], &bl[j >> 1][(j & 1) * 2]);
            }
    }
}

template<int MF, int NF, int CP>
__device__ __forceinline__ void acc_to_smem(float* Cs, float acc[MF][NF][4],
                                            int warp_m, int warp_n, int lane)
{
    const int lr = lane >> 2, lc = (lane & 3) * 2;
    #pragma unroll
    for (int i = 0; i < MF; ++i)
        #pragma unroll
        for (int j = 0; j < NF; ++j) {
            int m = warp_m + i * 16 + lr;
            int n = warp_n + j * 8 + lc;
            float* a = acc[i][j];
            *(float2*)(Cs + m * CP + n)       = make_float2(a[0], a[1]);
            *(float2*)(Cs + (m + 8) * CP + n) = make_float2(a[2], a[3]);
        }
}

// ---------------------------------------------------------------------------
// K0: precompute bf16 planes: feat hi+lo, W hi+lo
// ---------------------------------------------------------------------------
#define FEAT_V4 (CDIM * N_TOK / 4)
#define FEAT_BLK (FEAT_V4 / 256)
__global__ __launch_bounds__(256)
void k_cvt(const float* __restrict__ feat,
           const float* __restrict__ Wi, const float* __restrict__ Wj)
{
    int t = blockIdx.x * 256 + threadIdx.x;
    if (blockIdx.x < FEAT_BLK) {
        float4 v = ((const float4*)feat)[t];
        uint2 h, l; split4(v, h, l);
        ((uint2*)g_feat_h)[t] = h;
        ((uint2*)g_feat_l)[t] = l;
    } else {
        int w = t - FEAT_V4;
        float4 v = (w < 8192) ? ((const float4*)Wi)[w] : ((const float4*)Wj)[w - 8192];
        uint2 h, l; split4(v, h, l);
        ((uint2*)g_Wh)[w] = h;
        ((uint2*)g_Wl)[w] = l;
    }
}

// ---------------------------------------------------------------------------
// K1: F = W_half @ feat + bias ; grid 162 per half ; 3-term ; 8 K-chunks
//   buf: A hi/lo 128x40 = 10240 each ; B hi/lo 32x72 = 4608 each ; F_CH = 29696
//   Epilogue: half 0 -> Fh + Fl (Fi) ; half 1 -> Fh only (Fj)
// ---------------------------------------------------------------------------
#define F_CH 29696
__global__ __launch_bounds__(256, 2)
void k_F(const float* __restrict__ bi, const float* __restrict__ bj, int half)
{
    extern __shared__ __align__(16) char smem[];
    const uint32_t sb = smem_u32(smem);
    float* Cs = (float*)smem;
    const int tid = threadIdx.x, lane = tid & 31, warp = tid >> 5;
    const int warp_m = (warp >> 1) * 32, warp_n = (warp & 1) * 32;
    const int n0 = blockIdx.x * 64;
    const float* bias = half ? bj : bi;
    const __nv_bfloat16* Wh = g_Wh + (size_t)half * 128 * CDIM;
    const __nv_bfloat16* Wl = g_Wl + (size_t)half * 128 * CDIM;

    float acc[2][4][4] = {};

    auto prefetch = [&](int c, uint32_t buf) {
        stage_cp<128, 32>(buf,         Wh + c * 32, CDIM, tid);
        stage_cp<128, 32>(buf + 10240, Wl + c * 32, CDIM, tid);
        stage_cp<32, 64>(buf + 20480, g_feat_h + (size_t)(c * 32) * N_TOK + n0, N_TOK, tid);
        stage_cp<32, 64>(buf + 25088, g_feat_l + (size_t)(c * 32) * N_TOK + n0, N_TOK, tid);
        CP_COMMIT();
    };

    prefetch(0, sb);
    #pragma unroll
    for (int c = 0; c < 8; ++c) {
        uint32_t cur = sb + (c & 1) * F_CH;
        if (c + 1 < 8) { prefetch(c + 1, sb + ((c + 1) & 1) * F_CH); CP_WAIT1(); }
        else           { CP_WAIT0(); }
        __syncthreads();
        mma_chunk3<2, 2, false, true, 40, 72>(acc, cur, cur + 10240, cur + 20480, cur + 25088,
                                              warp_m, warp_n, lane);
        __syncthreads();
    }

    {   // bias
        const int lr = lane >> 2;
        #pragma unroll
        for (int i = 0; i < 2; ++i) {
            float b0 = bias[warp_m + i * 16 + lr];
            float b1 = bias[warp_m + i * 16 + lr + 8];
            #pragma unroll
            for (int j = 0; j < 4; ++j) {
                acc[i][j][0] += b0; acc[i][j][1] += b0;
                acc[i][j][2] += b1; acc[i][j][3] += b1;
            }
        }
    }

    acc_to_smem<2, 4, 68>(Cs, acc, warp_m, warp_n, lane);
    __syncthreads();
    for (int i = tid; i < 128 * 16; i += 256) {
        int row = i >> 4, col = (i & 15) << 2;
        float4 v = *(float4*)(Cs + row * 68 + col);
        size_t o = (size_t)(half * 128 + row) * N_TOK + n0 + col;
        if (half == 0) {
            uint2 h, l; split4(v, h, l);
            *(uint2*)(g_Fh + o) = h;
            *(uint2*)(g_Fl + (size_t)row * N_TOK + n0 + col) = l;
        } else {
            *(uint2*)(g_Fh + o) = hi4(v);     // Fj hi only (Gpart is 2-term)
        }
    }
}

// ---------------------------------------------------------------------------
// K2: Gpart[z][p][q] ; grid (54, 4) ; 6 K-chunks ; 2-TERM (A = Fj hi only)
//   buf: A hi 128x40 = 10240 ; B hi/lo 64x40 = 5120 each ; G_CH = 20480
// ---------------------------------------------------------------------------
#define G_CH 20480
__global__ __launch_bounds__(256, 2)
void k_Gpart()
{
    extern __shared__ __align__(16) char smem[];
    const uint32_t sb = smem_u32(smem);
    float* Cs = (float*)smem;
    const int tid = threadIdx.x, lane = tid & 31, warp = tid >> 5;
    const int warp_m = (warp >> 1) * 32, warp_n = (warp & 1) * 32;
    const int z = blockIdx.x, qt = blockIdx.y;
    const __nv_bfloat16* Ah = g_Fh + (size_t)HDIM * N_TOK + z * 192;
    const __nv_bfloat16* Bh = g_feat_h + (size_t)(qt * 64) * N_TOK + z * 192;
    const __nv_bfloat16* Bl = g_feat_l + (size_t)(qt * 64) * N_TOK + z * 192;

    float acc[2][4][4] = {};

    auto prefetch = [&](int c, uint32_t buf) {
        stage_cp<128, 32>(buf,         Ah + c * 32, N_TOK, tid);
        stage_cp<64, 32>(buf + 10240, Bh + c * 32, N_TOK, tid);
        stage_cp<64, 32>(buf + 15360, Bl + c * 32, N_TOK, tid);
        CP_COMMIT();
    };

    prefetch(0, sb);
    #pragma unroll
    for (int c = 0; c < 6; ++c) {
        uint32_t cur = sb + (c & 1) * G_CH;
        if (c + 1 < 6) { prefetch(c + 1, sb + ((c + 1) & 1) * G_CH); CP_WAIT1(); }
        else           { CP_WAIT0(); }
        __syncthreads();
        mma_chunk2<2, 2, false, false, 40, 40>(acc, cur, cur + 10240, cur + 15360,
                                               warp_m, warp_n, lane);
        __syncthreads();
    }

    acc_to_smem<2, 4, 68>(Cs, acc, warp_m, warp_n, lane);
    __syncthreads();
    float* outp = g_Gpart + (size_t)z * HDIM * CDIM + qt * 64;
    for (int i = tid; i < 128 * 16; i += 256) {
        int row = i >> 4, col = (i & 15) << 2;
        float4 v = *(float4*)(Cs + row * 68 + col);
        *(float4*)(outp + (size_t)row * CDIM + col) = v;
    }
}

// ---------------------------------------------------------------------------
// K3a: Gpart2[g] = sum of 3 chunks ; grid (32, 18)
// ---------------------------------------------------------------------------
__global__ __launch_bounds__(256)
void k_R1()
{
    const int t = blockIdx.x * 256 + threadIdx.x;
    const int g = blockIdx.y;
    const float4* gp = (const float4*)g_Gpart + (size_t)g * 3 * 8192;
    float4 v0 = gp[t];
    float4 v1 = gp[(size_t)8192 + t];
    float4 v2 = gp[(size_t)2 * 8192 + t];
    float4 r = make_float4(v0.x + v1.x + v2.x, v0.y + v1.y + v2.y,
                           v0.z + v1.z + v2.z, v0.w + v1.w + v2.w);
    ((float4*)g_Gpart2)[(size_t)g * 8192 + t] = r;
}

// ---------------------------------------------------------------------------
// K3b: G = (1/N) * sum of 18 partials -> bf16 hi plane only
// ---------------------------------------------------------------------------
__global__ __launch_bounds__(256)
void k_R2()
{
    const int t = blockIdx.x * 256 + threadIdx.x;
    const float4* gp = (const float4*)g_Gpart2;
    float4 v[18];
    #pragma unroll
    for (int g = 0; g < 18; ++g) v[g] = gp[(size_t)g * 8192 + t];
    float4 s4[9];
    #pragma unroll
    for (int g = 0; g < 9; ++g)
        s4[g] = make_float4(v[2*g].x + v[2*g+1].x, v[2*g].y + v[2*g+1].y,
                            v[2*g].z + v[2*g+1].z, v[2*g].w + v[2*g+1].w);
    const float s = 1.0f / N_TOK;
    float4 r = make_float4(
        (((s4[0].x + s4[1].x) + (s4[2].x + s4[3].x)) + ((s4[4].x + s4[5].x) + (s4[6].x + s4[7].x)) + s4[8].x) * s,
        (((s4[0].y + s4[1].y) + (s4[2].y + s4[3].y)) + ((s4[4].y + s4[5].y) + (s4[6].y + s4[7].y)) + s4[8].y) * s,
        (((s4[0].z + s4[1].z) + (s4[2].z + s4[3].z)) + ((s4[4].z + s4[5].z) + (s4[6].z + s4[7].z)) + s4[8].z) * s,
        (((s4[0].w + s4[1].w) + (s4[2].w + s4[3].w)) + ((s4[4].w + s4[5].w) + (s4[6].w + s4[7].w)) + s4[8].w) * s);
    ((uint2*)g_Gh)[t] = hi4(r);
}

// ---------------------------------------------------------------------------
// K4: out[q][n] = feat[q][n] + sum_p G[p][q]*Fi[p][n] ; 2-TERM (A = G hi only)
//   grid (162, 2) ; 4 K-chunks of 32 (p)
//   buf: A hi 32x136 = 8704 ; B hi/lo 32x72 = 4608 each ; O_CH = 17920
// ---------------------------------------------------------------------------
#define O_CH 17920
__global__ __launch_bounds__(256, 2)
void k_out(const float* __restrict__ feat, float* __restrict__ outp)
{
    extern __shared__ __align__(16) char smem[];
    const uint32_t sb = smem_u32(smem);
    float* Cs = (float*)smem;
    const int tid = threadIdx.x, lane = tid & 31, warp = tid >> 5;
    const int warp_m = (warp >> 1) * 32, warp_n = (warp & 1) * 32;
    const int n0 = blockIdx.x * 64, qh = blockIdx.y;

    float acc[2][4][4] = {};

    auto prefetch = [&](int c, uint32_t buf) {
        stage_cp<32, 128>(buf,         g_Gh + (size_t)(c * 32) * CDIM + qh * 128, CDIM, tid);
        stage_cp<32, 64>(buf + 8704,  g_Fh + (size_t)(c * 32) * N_TOK + n0, N_TOK, tid);
        stage_cp<32, 64>(buf + 13312, g_Fl + (size_t)(c * 32) * N_TOK + n0, N_TOK, tid);
        CP_COMMIT();
    };

    prefetch(0, sb);
    #pragma unroll
    for (int c = 0; c < 4; ++c) {
        uint32_t cur = sb + (c & 1) * O_CH;
        if (c + 1 < 4) { prefetch(c + 1, sb + ((c + 1) & 1) * O_CH); CP_WAIT1(); }
        else           { CP_WAIT0(); }
        __syncthreads();
        mma_chunk2<2, 2, true, true, 136, 72>(acc, cur, cur + 8704, cur + 13312,
                                              warp_m, warp_n, lane);
        __syncthreads();
    }

    acc_to_smem<2, 4, 68>(Cs, acc, warp_m, warp_n, lane);
    __syncthreads();
    for (int i = tid; i < 128 * 16; i += 256) {
        int row = i >> 4, col = (i & 15) << 2;
        size_t off = (size_t)(qh * 128 + row) * N_TOK + n0 + col;
        float4 v = *(float4*)(Cs + row * 68 + col);
        float4 f = *(const float4*)(feat + off);
        v.x += f.x; v.y += f.y; v.z += f.z; v.w += f.w;
        *(float4*)(outp + off) = v;
    }
}

// ---------------------------------------------------------------------------
extern "C" void kernel_launch(void* const* d_in, const int* in_sizes, int n_in,
                              void* d_out, int out_size)
{
    const float* feat = (const float*)d_in[0];
    const float* Wi   = (const float*)d_in[1];
    const float* bi   = (const float*)d_in[2];
    const float* Wj   = (const float*)d_in[3];
    const float* bj   = (const float*)d_in[4];
    float* outp = (float*)d_out;

    static cudaStream_t s1 = nullptr;
    static cudaEvent_t evA = nullptr, evB = nullptr;
    if (!s1) {
        cudaFuncSetAttribute(k_F,     cudaFuncAttributeMaxDynamicSharedMemorySize, 2 * F_CH);
        cudaFuncSetAttribute(k_Gpart, cudaFuncAttributeMaxDynamicSharedMemorySize, 2 * G_CH);
        cudaFuncSetAttribute(k_out,   cudaFuncAttributeMaxDynamicSharedMemorySize, 2 * O_CH);
        cudaStreamCreateWithFlags(&s1, cudaStreamNonBlocking);
        cudaEventCreateWithFlags(&evA, cudaEventDisableTiming);
        cudaEventCreateWithFlags(&evB, cudaEventDisableTiming);
    }

    // chain: cvt -> F(Fj) -> Gpart -> R1 -> R2 -> out ; F(Fi) concurrent on s1
    k_cvt <<<FEAT_BLK + 64, 256>>>(feat, Wi, Wj);
    k_F   <<<162, 256, 2 * F_CH>>>(bi, bj, 1);            // Fj half

    cudaEventRecord(evA, 0);
    cudaStreamWaitEvent(s1, evA, 0);
    k_F   <<<162, 256, 2 * F_CH, s1>>>(bi, bj, 0);        // Fi half (concurrent)

    k_Gpart <<<dim3(54, 4), 256, 2 * G_CH>>>();
    k_R1    <<<dim3(32, 18), 256>>>();
    k_R2    <<<32, 256>>>();

    cudaEventRecord(evB, s1);
    cudaStreamWaitEvent(0, evB, 0);
    k_out <<<dim3(162, 2), 256, 2 * O_CH>>>(feat, outp);
}

// round 17
// speedup vs baseline: 1.4796x; 1.4796x over previous
#include <cuda_runtime.h>
#include <cuda_bf16.h>
#include <cstdint>

#define N_TOK 10368
#define CDIM  256
#define HDIM  128
#define NZ    27          // token chunks of 384 for Gpart

// ---------------- scratch ----------------
__device__ __align__(16) __nv_bfloat16 g_feat_h[(size_t)CDIM * N_TOK];
__device__ __align__(16) __nv_bfloat16 g_feat_l[(size_t)CDIM * N_TOK];
__device__ __align__(16) __nv_bfloat16 g_Wh[(size_t)CDIM * CDIM];   // rows 0-127 Wi, 128-255 Wj
__device__ __align__(16) __nv_bfloat16 g_Wl[(size_t)CDIM * CDIM];
__device__ __align__(16) __nv_bfloat16 g_Fh[(size_t)CDIM * N_TOK];  // rows 0-127 Fi, 128-255 Fj
__device__ __align__(16) __nv_bfloat16 g_Fl[(size_t)HDIM * N_TOK];  // Fi lo only
__device__ float g_Gpart[(size_t)NZ * HDIM * CDIM];                 // [z][p][q] fp32 (3.5 MB)
__device__ __align__(16) __nv_bfloat16 g_Gh[(size_t)HDIM * CDIM];   // G/N bf16 hi
__device__ __align__(16) __nv_bfloat16 g_Gl[(size_t)HDIM * CDIM];   // G/N bf16 lo

// ---------------- helpers ----------------
__device__ __forceinline__ uint32_t smem_u32(const void* p) {
    uint32_t a;
    asm("{ .reg .u64 t; cvta.to.shared.u64 t, %1; cvt.u32.u64 %0, t; }" : "=r"(a) : "l"(p));
    return a;
}
__device__ __forceinline__ void ldsm4(uint32_t* r, uint32_t a) {
    asm volatile("ldmatrix.sync.aligned.m8n8.x4.shared.b16 {%0,%1,%2,%3}, [%4];"
                 : "=r"(r[0]), "=r"(r[1]), "=r"(r[2]), "=r"(r[3]) : "r"(a));
}
__device__ __forceinline__ void ldsm4t(uint32_t* r, uint32_t a) {
    asm volatile("ldmatrix.sync.aligned.m8n8.x4.trans.shared.b16 {%0,%1,%2,%3}, [%4];"
                 : "=r"(r[0]), "=r"(r[1]), "=r"(r[2]), "=r"(r[3]) : "r"(a));
}
__device__ __forceinline__ void mma_bf16(float* d, const uint32_t* a, const uint32_t* b) {
    asm volatile("mma.sync.aligned.m16n8k16.row.col.f32.bf16.bf16.f32 "
                 "{%0,%1,%2,%3}, {%4,%5,%6,%7}, {%8,%9}, {%0,%1,%2,%3};"
                 : "+f"(d[0]), "+f"(d[1]), "+f"(d[2]), "+f"(d[3])
                 : "r"(a[0]), "r"(a[1]), "r"(a[2]), "r"(a[3]), "r"(b[0]), "r"(b[1]));
}
__device__ __forceinline__ void cpa16(uint32_t dst, const void* src) {
    asm volatile("cp.async.cg.shared.global [%0], [%1], 16;" :: "r"(dst), "l"(src));
}
#define CP_COMMIT() asm volatile("cp.async.commit_group;" ::: "memory")
#define CP_WAIT0()  asm volatile("cp.async.wait_group 0;" ::: "memory")
#define CP_WAIT1()  asm volatile("cp.async.wait_group 1;" ::: "memory")

__device__ __forceinline__ void split4(float4 v, uint2& h, uint2& l) {
    __nv_bfloat16 h0 = __float2bfloat16_rn(v.x), h1 = __float2bfloat16_rn(v.y),
                  h2 = __float2bfloat16_rn(v.z), h3 = __float2bfloat16_rn(v.w);
    float l0 = v.x - __bfloat162float(h0), l1 = v.y - __bfloat162float(h1),
          l2 = v.z - __bfloat162float(h2), l3 = v.w - __bfloat162float(h3);
    h.x = (uint32_t)__bfloat16_as_ushort(h0) | ((uint32_t)__bfloat16_as_ushort(h1) << 16);
    h.y = (uint32_t)__bfloat16_as_ushort(h2) | ((uint32_t)__bfloat16_as_ushort(h3) << 16);
    l.x = (uint32_t)__bfloat16_as_ushort(__float2bfloat16_rn(l0)) |
          ((uint32_t)__bfloat16_as_ushort(__float2bfloat16_rn(l1)) << 16);
    l.y = (uint32_t)__bfloat16_as_ushort(__float2bfloat16_rn(l2)) |
          ((uint32_t)__bfloat16_as_ushort(__float2bfloat16_rn(l3)) << 16);
}
__device__ __forceinline__ uint2 hi4(float4 v) {
    __nv_bfloat16 h0 = __float2bfloat16_rn(v.x), h1 = __float2bfloat16_rn(v.y),
                  h2 = __float2bfloat16_rn(v.z), h3 = __float2bfloat16_rn(v.w);
    uint2 h;
    h.x = (uint32_t)__bfloat16_as_ushort(h0) | ((uint32_t)__bfloat16_as_ushort(h1) << 16);
    h.y = (uint32_t)__bfloat16_as_ushort(h2) | ((uint32_t)__bfloat16_as_ushort(h3) << 16);
    return h;
}

template<int ROWS, int KW>
__device__ __forceinline__ void stage_cp(uint32_t dst, const __nv_bfloat16* __restrict__ src,
                                         int ld, int tid)
{
    constexpr int RV = KW / 8;
    #pragma unroll
    for (int i = tid; i < ROWS * RV; i += 256) {
        int r = i / RV, c = (i % RV) * 8;
        cpa16(dst + (uint32_t)(r * (KW + 8) + c) * 2, src + (size_t)r * ld + c);
    }
}

template<bool AT, bool BT, int ASTR, int BSTR>
__device__ __forceinline__ void mma_addr(int warp_m, int warp_n, int lane,
                                         uint32_t& aBase, uint32_t& aStep, uint32_t& aM16,
                                         uint32_t& bBase, uint32_t& bStep, uint32_t& bN16)
{
    const int q = lane >> 3, rr = lane & 7;
    if (!AT) { aBase = (uint32_t)((warp_m + (q & 1) * 8 + rr) * ASTR + (q >> 1) * 8) * 2;
               aStep = 32; aM16 = 16 * ASTR * 2; }
    else     { aBase = (uint32_t)(((q >> 1) * 8 + rr) * ASTR + warp_m + (q & 1) * 8) * 2;
               aStep = 16 * ASTR * 2; aM16 = 32; }
    if (!BT) { bBase = (uint32_t)((warp_n + (q >> 1) * 8 + rr) * BSTR + (q & 1) * 8) * 2;
               bStep = 32; bN16 = 16 * BSTR * 2; }
    else     { bBase = (uint32_t)(((q & 1) * 8 + rr) * BSTR + warp_n + (q >> 1) * 8) * 2;
               bStep = 16 * BSTR * 2; bN16 = 32; }
}

// 3-term: acc += Ah*Bh + Ah*Bl + Al*Bh
template<int MF, int NF2, bool AT, bool BT, int ASTR, int BSTR>
__device__ __forceinline__ void mma_chunk3(float acc[MF][NF2 * 2][4],
                                           uint32_t aHi, uint32_t aLo,
                                           uint32_t bHi, uint32_t bLo,
                                           int warp_m, int warp_n, int lane)
{
    uint32_t aBase, aStep, aM16, bBase, bStep, bN16;
    mma_addr<AT, BT, ASTR, BSTR>(warp_m, warp_n, lane, aBase, aStep, aM16, bBase, bStep, bN16);

    #pragma unroll
    for (int ks = 0; ks < 2; ++ks) {
        uint32_t ah[MF][4], al[MF][4], bh[NF2][4], bl[NF2][4];
        uint32_t aA = aBase + ks * aStep, bA = bBase + ks * bStep;
        #pragma unroll
        for (int i = 0; i < MF; ++i) {
            if (AT) { ldsm4t(ah[i], aHi + aA + i * aM16); ldsm4t(al[i], aLo + aA + i * aM16); }
            else    { ldsm4 (ah[i], aHi + aA + i * aM16); ldsm4 (al[i], aLo + aA + i * aM16); }
        }
        #pragma unroll
        for (int g = 0; g < NF2; ++g) {
            if (BT) { ldsm4t(bh[g], bHi + bA + g * bN16); ldsm4t(bl[g], bLo + bA + g * bN16); }
            else    { ldsm4 (bh[g], bHi + bA + g * bN16); ldsm4 (bl[g], bLo + bA + g * bN16); }
        }
        #pragma unroll
        for (int i = 0; i < MF; ++i)
            #pragma unroll
            for (int j = 0; j < NF2 * 2; ++j) {
                mma_bf16(acc[i][j], ah[i], &bh[j >> 1][(j & 1) * 2]);
                mma_bf16(acc[i][j], ah[i], &bl[j >> 1][(j & 1) * 2]);
                mma_bf16(acc[i][j], al[i], &bh[j >> 1][(j & 1) * 2]);
            }
    }
}

// 2-term (A hi only): acc += Ah*Bh + Ah*Bl
template<int MF, int NF2, bool AT, bool BT, int ASTR, int BSTR>
__device__ __forceinline__ void mma_chunk2(float acc[MF][NF2 * 2][4],
                                           uint32_t aHi,
                                           uint32_t bHi, uint32_t bLo,
                                           int warp_m, int warp_n, int lane)
{
    uint32_t aBase, aStep, aM16, bBase, bStep, bN16;
    mma_addr<AT, BT, ASTR, BSTR>(warp_m, warp_n, lane, aBase, aStep, aM16, bBase, bStep, bN16);

    #pragma unroll
    for (int ks = 0; ks < 2; ++ks) {
        uint32_t ah[MF][4], bh[NF2][4], bl[NF2][4];
        uint32_t aA = aBase + ks * aStep, bA = bBase + ks * bStep;
        #pragma unroll
        for (int i = 0; i < MF; ++i) {
            if (AT) ldsm4t(ah[i], aHi + aA + i * aM16);
            else    ldsm4 (ah[i], aHi + aA + i * aM16);
        }
        #pragma unroll
        for (int g = 0; g < NF2; ++g) {
            if (BT) { ldsm4t(bh[g], bHi + bA + g * bN16); ldsm4t(bl[g], bLo + bA + g * bN16); }
            else    { ldsm4 (bh[g], bHi + bA + g * bN16); ldsm4 (bl[g], bLo + bA + g * bN16); }
        }
        #pragma unroll
        for (int i = 0; i < MF; ++i)
            #pragma unroll
            for (int j = 0; j < NF2 * 2; ++j) {
                mma_bf16(acc[i][j], ah[i], &bh[j >> 1][(j & 1) * 2]);
                mma_bf16(acc[i][j], ah[i], &bl[j >> 1][(j & 1) * 2]);
            }
    }
}

template<int MF, int NF, int CP>
__device__ __forceinline__ void acc_to_smem(float* Cs, float acc[MF][NF][4],
                                            int warp_m, int warp_n, int lane)
{
    const int lr = lane >> 2, lc = (lane & 3) * 2;
    #pragma unroll
    for (int i = 0; i < MF; ++i)
        #pragma unroll
        for (int j = 0; j < NF; ++j) {
            int m = warp_m + i * 16 + lr;
            int n = warp_n + j * 8 + lc;
            float* a = acc[i][j];
            *(float2*)(Cs + m * CP + n)       = make_float2(a[0], a[1]);
            *(float2*)(Cs + (m + 8) * CP + n) = make_float2(a[2], a[3]);
        }
}

// ---------------------------------------------------------------------------
// K0: precompute bf16 planes: feat hi+lo, W hi+lo
// ---------------------------------------------------------------------------
#define FEAT_V4 (CDIM * N_TOK / 4)
#define FEAT_BLK (FEAT_V4 / 256)
__global__ __launch_bounds__(256)
void k_cvt(const float* __restrict__ feat,
           const float* __restrict__ Wi, const float* __restrict__ Wj)
{
    int t = blockIdx.x * 256 + threadIdx.x;
    if (blockIdx.x < FEAT_BLK) {
        float4 v = ((const float4*)feat)[t];
        uint2 h, l; split4(v, h, l);
        ((uint2*)g_feat_h)[t] = h;
        ((uint2*)g_feat_l)[t] = l;
    } else {
        int w = t - FEAT_V4;
        float4 v = (w < 8192) ? ((const float4*)Wi)[w] : ((const float4*)Wj)[w - 8192];
        uint2 h, l; split4(v, h, l);
        ((uint2*)g_Wh)[w] = h;
        ((uint2*)g_Wl)[w] = l;
    }
}

// ---------------------------------------------------------------------------
// K1: F = W_half @ feat + bias ; grid 162 per half ; 3-term ; 8 K-chunks
//   buf: A hi/lo 128x40 = 10240 each ; B hi/lo 32x72 = 4608 each ; F_CH = 29696
//   Epilogue: half 0 -> Fh + Fl (Fi) ; half 1 -> Fh only (Fj; Gpart is 2-term)
// ---------------------------------------------------------------------------
#define F_CH 29696
__global__ __launch_bounds__(256, 2)
void k_F(const float* __restrict__ bi, const float* __restrict__ bj, int half)
{
    extern __shared__ __align__(16) char smem[];
    const uint32_t sb = smem_u32(smem);
    float* Cs = (float*)smem;
    const int tid = threadIdx.x, lane = tid & 31, warp = tid >> 5;
    const int warp_m = (warp >> 1) * 32, warp_n = (warp & 1) * 32;
    const int n0 = blockIdx.x * 64;
    const float* bias = half ? bj : bi;
    const __nv_bfloat16* Wh = g_Wh + (size_t)half * 128 * CDIM;
    const __nv_bfloat16* Wl = g_Wl + (size_t)half * 128 * CDIM;

    float acc[2][4][4] = {};

    auto prefetch = [&](int c, uint32_t buf) {
        stage_cp<128, 32>(buf,         Wh + c * 32, CDIM, tid);
        stage_cp<128, 32>(buf + 10240, Wl + c * 32, CDIM, tid);
        stage_cp<32, 64>(buf + 20480, g_feat_h + (size_t)(c * 32) * N_TOK + n0, N_TOK, tid);
        stage_cp<32, 64>(buf + 25088, g_feat_l + (size_t)(c * 32) * N_TOK + n0, N_TOK, tid);
        CP_COMMIT();
    };

    prefetch(0, sb);
    #pragma unroll
    for (int c = 0; c < 8; ++c) {
        uint32_t cur = sb + (c & 1) * F_CH;
        if (c + 1 < 8) { prefetch(c + 1, sb + ((c + 1) & 1) * F_CH); CP_WAIT1(); }
        else           { CP_WAIT0(); }
        __syncthreads();
        mma_chunk3<2, 2, false, true, 40, 72>(acc, cur, cur + 10240, cur + 20480, cur + 25088,
                                              warp_m, warp_n, lane);
        __syncthreads();
    }

    {   // bias
        const int lr = lane >> 2;
        #pragma unroll
        for (int i = 0; i < 2; ++i) {
            float b0 = bias[warp_m + i * 16 + lr];
            float b1 = bias[warp_m + i * 16 + lr + 8];
            #pragma unroll
            for (int j = 0; j < 4; ++j) {
                acc[i][j][0] += b0; acc[i][j][1] += b0;
                acc[i][j][2] += b1; acc[i][j][3] += b1;
            }
        }
    }

    acc_to_smem<2, 4, 68>(Cs, acc, warp_m, warp_n, lane);
    __syncthreads();
    for (int i = tid; i < 128 * 16; i += 256) {
        int row = i >> 4, col = (i & 15) << 2;
        float4 v = *(float4*)(Cs + row * 68 + col);
        size_t o = (size_t)(half * 128 + row) * N_TOK + n0 + col;
        if (half == 0) {
            uint2 h, l; split4(v, h, l);
            *(uint2*)(g_Fh + o) = h;
            *(uint2*)(g_Fl + (size_t)row * N_TOK + n0 + col) = l;
        } else {
            *(uint2*)(g_Fh + o) = hi4(v);
        }
    }
}

// ---------------------------------------------------------------------------
// K2: Gpart[z][p][q] ; grid (2, 4, 27): m-tile 64, q-tile 64, z = 384 tokens
//   12 K-chunks ; 2-TERM (A = Fj hi only) ; warp tile 16x32 (4x2 warps)
//   buf: A hi 64x40 = 5120 ; B hi/lo 64x40 = 5120 each ; G_CH = 15360
// ---------------------------------------------------------------------------
#define G_CH 15360
__global__ __launch_bounds__(256, 2)
void k_Gpart()
{
    extern __shared__ __align__(16) char smem[];
    const uint32_t sb = smem_u32(smem);
    float* Cs = (float*)smem;
    const int tid = threadIdx.x, lane = tid & 31, warp = tid >> 5;
    const int warp_m = (warp >> 1) * 16, warp_n = (warp & 1) * 32;
    const int mt = blockIdx.x, qt = blockIdx.y, z = blockIdx.z;
    const __nv_bfloat16* Ah = g_Fh + (size_t)(HDIM + mt * 64) * N_TOK + z * 384;
    const __nv_bfloat16* Bh = g_feat_h + (size_t)(qt * 64) * N_TOK + z * 384;
    const __nv_bfloat16* Bl = g_feat_l + (size_t)(qt * 64) * N_TOK + z * 384;

    float acc[1][4][4] = {};

    auto prefetch = [&](int c, uint32_t buf) {
        stage_cp<64, 32>(buf,         Ah + c * 32, N_TOK, tid);
        stage_cp<64, 32>(buf + 5120,  Bh + c * 32, N_TOK, tid);
        stage_cp<64, 32>(buf + 10240, Bl + c * 32, N_TOK, tid);
        CP_COMMIT();
    };

    prefetch(0, sb);
    #pragma unroll
    for (int c = 0; c < 12; ++c) {
        uint32_t cur = sb + (c & 1) * G_CH;
        if (c + 1 < 12) { prefetch(c + 1, sb + ((c + 1) & 1) * G_CH); CP_WAIT1(); }
        else            { CP_WAIT0(); }
        __syncthreads();
        mma_chunk2<1, 2, false, false, 40, 40>(acc, cur, cur + 5120, cur + 10240,
                                               warp_m, warp_n, lane);
        __syncthreads();
    }

    acc_to_smem<1, 4, 68>(Cs, acc, warp_m, warp_n, lane);
    __syncthreads();
    float* outp = g_Gpart + (size_t)z * HDIM * CDIM + (size_t)(mt * 64) * CDIM + qt * 64;
    for (int i = tid; i < 64 * 16; i += 256) {
        int row = i >> 4, col = (i & 15) << 2;
        float4 v = *(float4*)(Cs + row * 68 + col);
        *(float4*)(outp + (size_t)row * CDIM + col) = v;
    }
}

// ---------------------------------------------------------------------------
// K3: G = (1/N) * sum of 27 partials -> bf16 hi + lo planes ; grid 32
//   3 batches of 9-deep MLP loads
// ---------------------------------------------------------------------------
__global__ __launch_bounds__(256)
void k_R()
{
    const int t = blockIdx.x * 256 + threadIdx.x;    // 0..8191 float4 slots
    const float4* gp = (const float4*)g_Gpart;
    float4 acc = {0.f, 0.f, 0.f, 0.f};
    #pragma unroll
    for (int g0 = 0; g0 < 27; g0 += 9) {
        float4 v[9];
        #pragma unroll
        for (int g = 0; g < 9; ++g) v[g] = gp[(size_t)(g0 + g) * 8192 + t];
        float4 s = make_float4(
            ((v[0].x + v[1].x) + (v[2].x + v[3].x)) + ((v[4].x + v[5].x) + (v[6].x + v[7].x)) + v[8].x,
            ((v[0].y + v[1].y) + (v[2].y + v[3].y)) + ((v[4].y + v[5].y) + (v[6].y + v[7].y)) + v[8].y,
            ((v[0].z + v[1].z) + (v[2].z + v[3].z)) + ((v[4].z + v[5].z) + (v[6].z + v[7].z)) + v[8].z,
            ((v[0].w + v[1].w) + (v[2].w + v[3].w)) + ((v[4].w + v[5].w) + (v[6].w + v[7].w)) + v[8].w);
        acc.x += s.x; acc.y += s.y; acc.z += s.z; acc.w += s.w;
    }
    const float s = 1.0f / N_TOK;
    float4 r = make_float4(acc.x * s, acc.y * s, acc.z * s, acc.w * s);
    uint2 h, l; split4(r, h, l);
    ((uint2*)g_Gh)[t] = h;
    ((uint2*)g_Gl)[t] = l;
}

// ---------------------------------------------------------------------------
// K4: out[q][n] = feat[q][n] + sum_p G[p][q]*Fi[p][n] ; 3-term ; grid (162, 2)
//   buf: A hi/lo 32x136 = 8704 each ; B hi/lo 32x72 = 4608 each ; O_CH = 26624
// ---------------------------------------------------------------------------
#define O_CH 26624
__global__ __launch_bounds__(256, 2)
void k_out(const float* __restrict__ feat, float* __restrict__ outp)
{
    extern __shared__ __align__(16) char smem[];
    const uint32_t sb = smem_u32(smem);
    float* Cs = (float*)smem;
    const int tid = threadIdx.x, lane = tid & 31, warp = tid >> 5;
    const int warp_m = (warp >> 1) * 32, warp_n = (warp & 1) * 32;
    const int n0 = blockIdx.x * 64, qh = blockIdx.y;

    float acc[2][4][4] = {};

    auto prefetch = [&](int c, uint32_t buf) {
        stage_cp<32, 128>(buf,         g_Gh + (size_t)(c * 32) * CDIM + qh * 128, CDIM, tid);
        stage_cp<32, 128>(buf + 8704,  g_Gl + (size_t)(c * 32) * CDIM + qh * 128, CDIM, tid);
        stage_cp<32, 64>(buf + 17408, g_Fh + (size_t)(c * 32) * N_TOK + n0, N_TOK, tid);
        stage_cp<32, 64>(buf + 22016, g_Fl + (size_t)(c * 32) * N_TOK + n0, N_TOK, tid);
        CP_COMMIT();
    };

    prefetch(0, sb);
    #pragma unroll
    for (int c = 0; c < 4; ++c) {
        uint32_t cur = sb + (c & 1) * O_CH;
        if (c + 1 < 4) { prefetch(c + 1, sb + ((c + 1) & 1) * O_CH); CP_WAIT1(); }
        else           { CP_WAIT0(); }
        __syncthreads();
        mma_chunk3<2, 2, true, true, 136, 72>(acc, cur, cur + 8704, cur + 17408, cur + 22016,
                                              warp_m, warp_n, lane);
        __syncthreads();
    }

    acc_to_smem<2, 4, 68>(Cs, acc, warp_m, warp_n, lane);
    __syncthreads();
    for (int i = tid; i < 128 * 16; i += 256) {
        int row = i >> 4, col = (i & 15) << 2;
        size_t off = (size_t)(qh * 128 + row) * N_TOK + n0 + col;
        float4 v = *(float4*)(Cs + row * 68 + col);
        float4 f = *(const float4*)(feat + off);
        v.x += f.x; v.y += f.y; v.z += f.z; v.w += f.w;
        *(float4*)(outp + off) = v;
    }
}

// ---------------------------------------------------------------------------
extern "C" void kernel_launch(void* const* d_in, const int* in_sizes, int n_in,
                              void* d_out, int out_size)
{
    const float* feat = (const float*)d_in[0];
    const float* Wi   = (const float*)d_in[1];
    const float* bi   = (const float*)d_in[2];
    const float* Wj   = (const float*)d_in[3];
    const float* bj   = (const float*)d_in[4];
    float* outp = (float*)d_out;

    static cudaStream_t s1 = nullptr;
    static cudaEvent_t evA = nullptr, evB = nullptr;
    if (!s1) {
        cudaFuncSetAttribute(k_F,     cudaFuncAttributeMaxDynamicSharedMemorySize, 2 * F_CH);
        cudaFuncSetAttribute(k_Gpart, cudaFuncAttributeMaxDynamicSharedMemorySize, 2 * G_CH);
        cudaFuncSetAttribute(k_out,   cudaFuncAttributeMaxDynamicSharedMemorySize, 2 * O_CH);
        cudaStreamCreateWithFlags(&s1, cudaStreamNonBlocking);
        cudaEventCreateWithFlags(&evA, cudaEventDisableTiming);
        cudaEventCreateWithFlags(&evB, cudaEventDisableTiming);
    }

    // chain: cvt -> F(Fj) -> Gpart -> R -> out ; F(Fi) concurrent on s1
    k_cvt <<<FEAT_BLK + 64, 256>>>(feat, Wi, Wj);
    k_F   <<<162, 256, 2 * F_CH>>>(bi, bj, 1);            // Fj half

    cudaEventRecord(evA, 0);
    cudaStreamWaitEvent(s1, evA, 0);
    k_F   <<<162, 256, 2 * F_CH, s1>>>(bi, bj, 0);        // Fi half (concurrent)

    k_Gpart <<<dim3(2, 4, 27), 256, 2 * G_CH>>>();
    k_R     <<<32, 256>>>();

    cudaEventRecord(evB, s1);
    cudaStreamWaitEvent(0, evB, 0);
    k_out <<<dim3(162, 2), 256, 2 * O_CH>>>(feat, outp);
}